// round 6
// baseline (speedup 1.0000x reference)
#include <cuda_runtime.h>
#include <math.h>

// ---------------- dims ----------------
#define B_      128
#define K_      128
#define DIN     256
#define PROJ    64
#define DMODEL  128
#define NLAYER  4
#define PLEN    8
#define STRIDE  4
#define DINNER  256
#define DSTATE  16
#define DTRANK  8
#define NPATCH  32
#define NSEQ    (B_*PROJ)        // 8192

typedef unsigned long long ull;
struct __align__(16) ull2 { ull x, y; };

// ---------------- scratch (no cudaMalloc) ----------------
__device__ float  g_projT[B_*PROJ*K_];     // [b][c][k] : 4 MB
__device__ float  g_part[1024];
__device__ float  g_scale;
__device__ float  g_ypred[NSEQ];
// transformed weights
__device__ float4 g_wp4 [64*64];           // [k4][j]     proj_w
__device__ float4 g_win [NLAYER*32*512];   // [L][k4][j]  inproj
__device__ float4 g_wout[NLAYER*64*128];   // [L][d4][m]  outproj
__device__ float4 g_wx4 [NLAYER*64*40];    // [L][d4][q]  xproj
__device__ float  g_negA[NLAYER*16*256];   // [L][n][d] = -exp(A_log)*log2(e)
__device__ float  g_dtw [NLAYER*8*256];    // [L][r][d]
__device__ float  g_convT[NLAYER*4*256];   // [L][i][d]

#define LOG2E 1.4426950408889634f

// ---------------- helpers ----------------
__device__ __forceinline__ void fma2(ull &d, ull a, ull b) {
    asm("fma.rn.f32x2 %0, %1, %2, %0;" : "+l"(d) : "l"(a), "l"(b));
}
__device__ __forceinline__ float f2sum(ull v) {
    float lo, hi;
    asm("mov.b64 {%0,%1}, %2;" : "=f"(lo), "=f"(hi) : "l"(v));
    return lo + hi;
}
__device__ __forceinline__ float ex2f(float x) {
    float r;
    asm("ex2.approx.f32 %0, %1;" : "=f"(r) : "f"(x));
    return r;
}
__device__ __forceinline__ float siluf(float x) { return x / (1.0f + __expf(-x)); }
__device__ __forceinline__ float softplusf(float x) {
    return fmaxf(x, 0.0f) + __logf(1.0f + __expf(-fabsf(x)));
}

// =================================================================
// Kernel 0: one-time weight transform
// =================================================================
#define TR_TOTAL 141312
__global__ void k_transpose(const float* __restrict__ pw,
                            const float* __restrict__ inw,
                            const float* __restrict__ outw,
                            const float* __restrict__ xw,
                            const float* __restrict__ Alog,
                            const float* __restrict__ dtw,
                            const float* __restrict__ cw) {
    int idx = blockIdx.x*256 + threadIdx.x;
    if (idx < 4096) {                                   // proj_w
        int j = idx >> 6, k4 = idx & 63;
        g_wp4[k4*64 + j] = *(const float4*)(pw + j*DIN + k4*4);
        return;
    }
    idx -= 4096;
    if (idx < 65536) {                                  // inproj
        int jf = idx >> 5, k4 = idx & 31;               // jf = L*512+j
        int L = jf >> 9, j = jf & 511;
        g_win[(L*32 + k4)*512 + j] = *(const float4*)(inw + (size_t)jf*DMODEL + k4*4);
        return;
    }
    idx -= 65536;
    if (idx < 32768) {                                  // outproj
        int mf = idx >> 6, d4 = idx & 63;               // mf = L*128+m
        int L = mf >> 7, m = mf & 127;
        g_wout[(L*64 + d4)*128 + m] = *(const float4*)(outw + (size_t)mf*DINNER + d4*4);
        return;
    }
    idx -= 32768;
    if (idx < 10240) {                                  // xproj
        int qf = idx >> 6, d4 = idx & 63;               // qf = L*40+q
        int L = qf / 40, q = qf % 40;
        g_wx4[(L*64 + d4)*40 + q] = *(const float4*)(xw + (size_t)qf*DINNER + d4*4);
        return;
    }
    idx -= 10240;
    if (idx < 16384) {                                  // -exp(A_log)*log2e
        int df = idx >> 4, n = idx & 15;                // df = L*256+d
        int L = df >> 8, d = df & 255;
        g_negA[(L*16 + n)*256 + d] = -expf(Alog[df*16 + n]) * LOG2E;
        return;
    }
    idx -= 16384;
    if (idx < 8192) {                                   // dtproj_w
        int df = idx >> 3, r = idx & 7;
        int L = df >> 8, d = df & 255;
        g_dtw[(L*8 + r)*256 + d] = dtw[df*8 + r];
        return;
    }
    idx -= 8192;
    if (idx < 4096) {                                   // conv_w
        int df = idx >> 2, i = idx & 3;
        int L = df >> 8, d = df & 255;
        g_convT[(L*4 + i)*256 + d] = cw[df*4 + i];
    }
}

// =================================================================
// Kernel 1: input projection, 16 rows/block
// =================================================================
__global__ void __launch_bounds__(256) k_proj(const float* __restrict__ x,
                                              const float* __restrict__ pb) {
    __shared__ float sx[256*20];
    __shared__ float red[8];
    int tid = threadIdx.x, bid = blockIdx.x;
    int rowb = bid*16;
    for (int i = tid; i < 16*256; i += 256) {
        int r = i >> 8, k = i & 255;
        sx[k*20 + r] = x[(size_t)(rowb + r)*DIN + k];
    }
    __syncthreads();

    int j = tid & 63, rgrp = tid >> 6;
    float bj = pb[j];
    float a0 = bj, a1 = bj, a2 = bj, a3 = bj;
#pragma unroll 4
    for (int k4 = 0; k4 < 64; k4++) {
        float4 w = g_wp4[k4*64 + j];
        float4 v;
        v = *(const float4*)(sx + (k4*4+0)*20 + rgrp*4);
        a0=fmaf(w.x,v.x,a0); a1=fmaf(w.x,v.y,a1); a2=fmaf(w.x,v.z,a2); a3=fmaf(w.x,v.w,a3);
        v = *(const float4*)(sx + (k4*4+1)*20 + rgrp*4);
        a0=fmaf(w.y,v.x,a0); a1=fmaf(w.y,v.y,a1); a2=fmaf(w.y,v.z,a2); a3=fmaf(w.y,v.w,a3);
        v = *(const float4*)(sx + (k4*4+2)*20 + rgrp*4);
        a0=fmaf(w.z,v.x,a0); a1=fmaf(w.z,v.y,a1); a2=fmaf(w.z,v.z,a2); a3=fmaf(w.z,v.w,a3);
        v = *(const float4*)(sx + (k4*4+3)*20 + rgrp*4);
        a0=fmaf(w.w,v.x,a0); a1=fmaf(w.w,v.y,a1); a2=fmaf(w.w,v.z,a2); a3=fmaf(w.w,v.w,a3);
    }
    a0 = fminf(5.0f, fmaxf(-5.0f, a0));
    a1 = fminf(5.0f, fmaxf(-5.0f, a1));
    a2 = fminf(5.0f, fmaxf(-5.0f, a2));
    a3 = fminf(5.0f, fmaxf(-5.0f, a3));
    int b = rowb >> 7, k0 = (bid & 7) * 16;
    float4 o = make_float4(a0, a1, a2, a3);
    *(float4*)(g_projT + ((size_t)(b*PROJ + j))*K_ + k0 + rgrp*4) = o;

    float s = fabsf(a0)+fabsf(a1)+fabsf(a2)+fabsf(a3);
#pragma unroll
    for (int off = 16; off; off >>= 1) s += __shfl_xor_sync(0xffffffffu, s, off);
    if ((tid & 31) == 0) red[tid >> 5] = s;
    __syncthreads();
    if (tid == 0) {
        float t = 0.0f;
#pragma unroll
        for (int i = 0; i < 8; i++) t += red[i];
        g_part[bid] = t;
    }
}

// =================================================================
// Kernel 2: reduce abs partials -> g_scale
// =================================================================
__global__ void k_reduce() {
    int tid = threadIdx.x;
    __shared__ float red[8];
    float s = 0.0f;
    for (int i = tid; i < 1024; i += 256) s += g_part[i];
#pragma unroll
    for (int o = 16; o; o >>= 1) s += __shfl_xor_sync(0xffffffffu, s, o);
    if ((tid & 31) == 0) red[tid >> 5] = s;
    __syncthreads();
    if (tid == 0) {
        float t = 0.0f;
#pragma unroll
        for (int i = 0; i < 8; i++) t += red[i];
        g_scale = t * (1.0f/(float)(B_*K_*PROJ)) + 1e-6f;
    }
}

// =================================================================
// Mega-kernel: one block per sequence
// =================================================================
#define OFF_H    0
#define OFF_HN   4096
#define OFF_XR   8192       // 32 x 512 : [xc | res], xc overwritten by ys
#define OFF_DBL  24576      // 32 x 40
#define OFF_XN   25856      // 132 (+pad)
#define OFF_RED  25992
#define OFF_MISC 26024
#define SMEM_FLOATS 26032   // 104128 B -> 2 blocks/SM (reg-bound anyway)

__device__ __forceinline__ float block_reduce256(float v, float* red) {
#pragma unroll
    for (int o = 16; o; o >>= 1) v += __shfl_xor_sync(0xffffffffu, v, o);
    int wid = threadIdx.x >> 5;
    if ((threadIdx.x & 31) == 0) red[wid] = v;
    __syncthreads();
    if (threadIdx.x == 0) {
        float t = 0.0f;
#pragma unroll
        for (int i = 0; i < 8; i++) t += red[i];
        red[0] = t;
    }
    __syncthreads();
    float r = red[0];
    __syncthreads();
    return r;
}

__global__ void __launch_bounds__(256, 2) k_mamba(
    const float* __restrict__ emb_w,   const float* __restrict__ emb_b,
    const float* __restrict__ norm_w,  const float* __restrict__ conv_b,
    const float* __restrict__ dtproj_b,const float* __restrict__ D_p,
    const float* __restrict__ normf_w, const float* __restrict__ headb_w,
    const float* __restrict__ headb_b)
{
    extern __shared__ float sm[];
    float* sh    = sm + OFF_H;
    float* shn   = sm + OFF_HN;
    float* sxr   = sm + OFF_XR;
    float* sdbl  = sm + OFF_DBL;
    float* sxn   = sm + OFF_XN;
    float* sred  = sm + OFF_RED;
    float* smisc = sm + OFF_MISC;

    const int tid = threadIdx.x;
    const int seq = blockIdx.x;
    const int b   = seq >> 6;
    const int c   = seq & 63;

    // -------- Phase A: scale + instance norm over K --------
    const float inv_s = 1.0f / g_scale;
    float val = 0.0f;
    if (tid < K_) val = g_projT[((size_t)(b*PROJ + c))*K_ + tid] * inv_s;
    float su = block_reduce256(tid < K_ ? val : 0.0f, sred);
    float sq = block_reduce256(tid < K_ ? val*val : 0.0f, sred);
    float mu  = su * (1.0f/(float)K_);
    float var = sq * (1.0f/(float)K_) - mu*mu;
    float sd  = sqrtf(var + 1e-5f);
    float rsd = 1.0f / sd;
    if (tid < K_) sxn[tid] = (val - mu) * rsd;
    if (tid == 0) { smisc[0] = mu; smisc[1] = sd; }
    __syncthreads();
    if (tid < STRIDE) sxn[K_ + tid] = sxn[K_ - 1];
    __syncthreads();

    // -------- Phase B: patch embedding -> h --------
    {
        int m  = tid & 127;
        int n0 = tid >> 7;
        float4 e0 = *(const float4*)(emb_w + m*PLEN);
        float4 e1 = *(const float4*)(emb_w + m*PLEN + 4);
        float  eb = emb_b[m];
        for (int n = n0; n < NPATCH; n += 2) {
            const float* xp = sxn + n*STRIDE;
            float v = eb;
            v = fmaf(e0.x, xp[0], v); v = fmaf(e0.y, xp[1], v);
            v = fmaf(e0.z, xp[2], v); v = fmaf(e0.w, xp[3], v);
            v = fmaf(e1.x, xp[4], v); v = fmaf(e1.y, xp[5], v);
            v = fmaf(e1.z, xp[6], v); v = fmaf(e1.w, xp[7], v);
            sh[n*DMODEL + m] = v;
        }
    }
    __syncthreads();

    // -------- Phase C: 4 Mamba layers --------
#pragma unroll 1
    for (int L = 0; L < NLAYER; L++) {
        // 1. rmsnorm(h)*norm_w -> hn
        {
            int wid = tid >> 5, lane = tid & 31;
            float4 wv4 = *(const float4*)(norm_w + L*DMODEL + lane*4);
#pragma unroll
            for (int r = wid*4; r < wid*4 + 4; r++) {
                float4 hv = *(const float4*)(sh + r*DMODEL + lane*4);
                float ss = hv.x*hv.x + hv.y*hv.y + hv.z*hv.z + hv.w*hv.w;
#pragma unroll
                for (int o = 16; o; o >>= 1) ss += __shfl_xor_sync(0xffffffffu, ss, o);
                float rms = rsqrtf(ss*(1.0f/(float)DMODEL) + 1e-5f);
                float4 ov;
                ov.x = hv.x*rms*wv4.x; ov.y = hv.y*rms*wv4.y;
                ov.z = hv.z*rms*wv4.z; ov.w = hv.w*rms*wv4.w;
                *(float4*)(shn + r*DMODEL + lane*4) = ov;
            }
        }
        __syncthreads();

        // 2. inproj (2-j tile) + fused conv+bias+silu on the xc half
        {
            const ull2* Wb = (const ull2*)(g_win + (size_t)L*32*512);
            float cw0 = g_convT[(L*4+0)*256 + tid];
            float cw1 = g_convT[(L*4+1)*256 + tid];
            float cw2 = g_convT[(L*4+2)*256 + tid];
            float cw3 = g_convT[(L*4+3)*256 + tid];
            float cb  = conv_b[L*DINNER + tid];
            float cx0 = 0.0f, cx1 = 0.0f, cx2 = 0.0f;   // conv state across t
#pragma unroll 1
            for (int th = 0; th < 2; th++) {
                const int tbase = th*16;
                ull acc0[16], acc1[16];
#pragma unroll
                for (int t = 0; t < 16; t++) { acc0[t] = 0ULL; acc1[t] = 0ULL; }
                ull2 w0 = Wb[tid];
                ull2 w1 = Wb[tid + 256];
#pragma unroll 1
                for (int k4 = 0; k4 < 32; k4++) {
                    ull2 wc0 = w0, wc1 = w1;
                    int nk = (k4 < 31) ? k4 + 1 : 31;
                    w0 = Wb[nk*512 + tid];
                    w1 = Wb[nk*512 + tid + 256];
                    const float* ap = shn + tbase*DMODEL + k4*4;
#pragma unroll
                    for (int t = 0; t < 16; t++) {
                        ull2 a = *(const ull2*)(ap + t*DMODEL);
                        fma2(acc0[t], wc0.x, a.x); fma2(acc0[t], wc0.y, a.y);
                        fma2(acc1[t], wc1.x, a.x); fma2(acc1[t], wc1.y, a.y);
                    }
                }
#pragma unroll
                for (int t = 0; t < 16; t++) {
                    float xc = f2sum(acc0[t]);
                    float co = fmaf(cw0, cx0, fmaf(cw1, cx1, fmaf(cw2, cx2, fmaf(cw3, xc, cb))));
                    cx0 = cx1; cx1 = cx2; cx2 = xc;
                    sxr[(tbase+t)*512 + tid]       = siluf(co);
                    sxr[(tbase+t)*512 + 256 + tid] = f2sum(acc1[t]);
                }
            }
        }
        __syncthreads();

        // 3. xproj: warp owns 4 t-rows, lanes own q (q and q+32)
        {
            int wid = tid >> 5, lane = tid & 31;
            int t0 = wid * 4;
            bool hasB = lane < 8;
            int q2 = 32 + lane;
            const ull2* Wb = (const ull2*)(g_wx4 + (size_t)L*64*40);
            ull accA[4], accB[4];
#pragma unroll
            for (int t = 0; t < 4; t++) { accA[t] = 0ULL; accB[t] = 0ULL; }
#pragma unroll 2
            for (int d4 = 0; d4 < 64; d4++) {
                ull2 w1 = Wb[d4*40 + lane];
                ull2 w2 = hasB ? Wb[d4*40 + q2] : w1;
#pragma unroll
                for (int t = 0; t < 4; t++) {
                    ull2 a = *(const ull2*)(sxr + (t0+t)*512 + d4*4);
                    fma2(accA[t], w1.x, a.x); fma2(accA[t], w1.y, a.y);
                    fma2(accB[t], w2.x, a.x); fma2(accB[t], w2.y, a.y);
                }
            }
#pragma unroll
            for (int t = 0; t < 4; t++) {
                sdbl[(t0+t)*40 + lane] = f2sum(accA[t]);
                if (hasB) sdbl[(t0+t)*40 + q2] = f2sum(accB[t]);
            }
        }
        __syncthreads();

        // 4. selective scan (thread d owns channel d), vectorized param reads
        {
            int d = tid;
            float dw[DTRANK];
#pragma unroll
            for (int r = 0; r < DTRANK; r++) dw[r] = g_dtw[(L*8 + r)*256 + d];
            float dtb = dtproj_b[L*DINNER + d];
            float Dp  = D_p[L*DINNER + d];
            float nA[DSTATE];          // pre-scaled by log2(e), negated
#pragma unroll
            for (int n = 0; n < DSTATE; n++) nA[n] = g_negA[(L*16 + n)*256 + d];
            float st[DSTATE];
#pragma unroll
            for (int n = 0; n < DSTATE; n++) st[n] = 0.0f;

#pragma unroll 1
            for (int t = 0; t < NPATCH; t++) {
                const float4* db4 = (const float4*)(sdbl + t*40);
                float4 q0 = db4[0], q1 = db4[1];                       // dt[0..7]
                float dtv = dtb;
                dtv = fmaf(dw[0], q0.x, dtv); dtv = fmaf(dw[1], q0.y, dtv);
                dtv = fmaf(dw[2], q0.z, dtv); dtv = fmaf(dw[3], q0.w, dtv);
                dtv = fmaf(dw[4], q1.x, dtv); dtv = fmaf(dw[5], q1.y, dtv);
                dtv = fmaf(dw[6], q1.z, dtv); dtv = fmaf(dw[7], q1.w, dtv);
                dtv = softplusf(dtv);

                float u = sxr[t*512 + d];
                float du = dtv * u;
                float Bv[DSTATE], Cv[DSTATE];
                {
                    float4 b0 = db4[2], b1 = db4[3], b2 = db4[4], b3 = db4[5];
                    Bv[0]=b0.x; Bv[1]=b0.y; Bv[2]=b0.z; Bv[3]=b0.w;
                    Bv[4]=b1.x; Bv[5]=b1.y; Bv[6]=b1.z; Bv[7]=b1.w;
                    Bv[8]=b2.x; Bv[9]=b2.y; Bv[10]=b2.z; Bv[11]=b2.w;
                    Bv[12]=b3.x; Bv[13]=b3.y; Bv[14]=b3.z; Bv[15]=b3.w;
                    float4 c0 = db4[6], c1 = db4[7], c2 = db4[8], c3 = db4[9];
                    Cv[0]=c0.x; Cv[1]=c0.y; Cv[2]=c0.z; Cv[3]=c0.w;
                    Cv[4]=c1.x; Cv[5]=c1.y; Cv[6]=c1.z; Cv[7]=c1.w;
                    Cv[8]=c2.x; Cv[9]=c2.y; Cv[10]=c2.z; Cv[11]=c2.w;
                    Cv[12]=c3.x; Cv[13]=c3.y; Cv[14]=c3.z; Cv[15]=c3.w;
                }
                float y = 0.0f;
#pragma unroll
                for (int n = 0; n < DSTATE; n++) {
                    float dA = ex2f(dtv * nA[n]);
                    st[n] = fmaf(st[n], dA, du * Bv[n]);
                    y = fmaf(st[n], Cv[n], y);
                }
                y = fmaf(u, Dp, y);
                float rv = sxr[t*512 + DINNER + d];
                sxr[t*512 + d] = y * siluf(rv);
            }
        }
        __syncthreads();

        // 5. outproj: 4-m x 4-t register tile, fused residual add into sh
        {
            int m2 = tid & 31, tg = tid >> 5;      // tg 0..7, 4 t each
            int tb = tg * 4;
            const ull2* Wb = (const ull2*)(g_wout + (size_t)L*64*128);
            ull acc[4][4];                          // [mi][t]
#pragma unroll
            for (int mi = 0; mi < 4; mi++)
#pragma unroll
                for (int t = 0; t < 4; t++) acc[mi][t] = 0ULL;
            ull2 w0 = Wb[m2], w1 = Wb[m2+32], w2 = Wb[m2+64], w3 = Wb[m2+96];
#pragma unroll 1
            for (int d4 = 0; d4 < 64; d4++) {
                ull2 c0 = w0, c1 = w1, c2 = w2, c3 = w3;
                int nd = (d4 < 63) ? d4 + 1 : 63;
                w0 = Wb[nd*128 + m2];      w1 = Wb[nd*128 + m2 + 32];
                w2 = Wb[nd*128 + m2 + 64]; w3 = Wb[nd*128 + m2 + 96];
                const float* ap = sxr + tb*512 + d4*4;
#pragma unroll
                for (int t = 0; t < 4; t++) {
                    ull2 a = *(const ull2*)(ap + t*512);
                    fma2(acc[0][t], c0.x, a.x); fma2(acc[0][t], c0.y, a.y);
                    fma2(acc[1][t], c1.x, a.x); fma2(acc[1][t], c1.y, a.y);
                    fma2(acc[2][t], c2.x, a.x); fma2(acc[2][t], c2.y, a.y);
                    fma2(acc[3][t], c3.x, a.x); fma2(acc[3][t], c3.y, a.y);
                }
            }
#pragma unroll
            for (int t = 0; t < 4; t++) {
#pragma unroll
                for (int mi = 0; mi < 4; mi++) {
                    int m = m2 + mi*32;
                    sh[(tb+t)*DMODEL + m] += f2sum(acc[mi][t]);
                }
            }
        }
        __syncthreads();
    }

    // -------- Phase D: final rmsnorm + headb dot + denorm --------
    {
        int wid = tid >> 5, lane = tid & 31;
        float4 wv4 = *(const float4*)(normf_w + lane*4);
#pragma unroll
        for (int r = wid*4; r < wid*4 + 4; r++) {
            float4 hv = *(const float4*)(sh + r*DMODEL + lane*4);
            float ss = hv.x*hv.x + hv.y*hv.y + hv.z*hv.z + hv.w*hv.w;
#pragma unroll
            for (int o = 16; o; o >>= 1) ss += __shfl_xor_sync(0xffffffffu, ss, o);
            float rms = rsqrtf(ss*(1.0f/(float)DMODEL) + 1e-5f);
            float4 ov;
            ov.x = hv.x*rms*wv4.x; ov.y = hv.y*rms*wv4.y;
            ov.z = hv.z*rms*wv4.z; ov.w = hv.w*rms*wv4.w;
            *(float4*)(shn + r*DMODEL + lane*4) = ov;
        }
    }
    __syncthreads();

    float loc = 0.0f;
    for (int o = tid; o < NPATCH*DMODEL; o += 256) loc += shn[o]*headb_w[o];
    float tot = block_reduce256(loc, sred);
    if (tid == 0) {
        float yv = tot + headb_b[0];
        g_ypred[seq] = yv * smisc[1] + smisc[0];
    }
}

// =================================================================
// Kernel 4: final head  (128,64) @ (64,2)
// =================================================================
__global__ void k_head(const float* __restrict__ head_w,
                       const float* __restrict__ head_b,
                       float* __restrict__ out) {
    int tid = threadIdx.x;
    int b = tid >> 1, o = tid & 1;
    float acc = head_b[o];
    const float* w = head_w + o*PROJ;
#pragma unroll 8
    for (int c = 0; c < PROJ; c++) acc = fmaf(g_ypred[b*PROJ + c], w[c], acc);
    out[b*2 + o] = acc;
}

// =================================================================
// launch
// =================================================================
extern "C" void kernel_launch(void* const* d_in, const int* in_sizes, int n_in,
                              void* d_out, int out_size) {
    const float* x         = (const float*)d_in[0];
    const float* proj_w    = (const float*)d_in[1];
    const float* proj_b    = (const float*)d_in[2];
    const float* emb_w     = (const float*)d_in[3];
    const float* emb_b     = (const float*)d_in[4];
    const float* norm_w    = (const float*)d_in[5];
    const float* inproj_w  = (const float*)d_in[6];
    const float* conv_w    = (const float*)d_in[7];
    const float* conv_b    = (const float*)d_in[8];
    const float* xproj_w   = (const float*)d_in[9];
    const float* dtproj_w  = (const float*)d_in[10];
    const float* dtproj_b  = (const float*)d_in[11];
    const float* A_log     = (const float*)d_in[12];
    const float* D_p       = (const float*)d_in[13];
    const float* outproj_w = (const float*)d_in[14];
    const float* normf_w   = (const float*)d_in[15];
    const float* headb_w   = (const float*)d_in[16];
    const float* headb_b   = (const float*)d_in[17];
    const float* head_w    = (const float*)d_in[18];
    const float* head_b    = (const float*)d_in[19];

    cudaFuncSetAttribute(k_mamba, cudaFuncAttributeMaxDynamicSharedMemorySize,
                         SMEM_FLOATS * sizeof(float));

    k_transpose<<<(TR_TOTAL + 255)/256, 256>>>(proj_w, inproj_w, outproj_w,
                                               xproj_w, A_log, dtproj_w, conv_w);
    k_proj<<<(B_*K_)/16, 256>>>(x, proj_b);
    k_reduce<<<1, 256>>>();
    k_mamba<<<NSEQ, 256, SMEM_FLOATS * sizeof(float)>>>(
        emb_w, emb_b, norm_w, conv_b, dtproj_b, D_p, normf_w, headb_w, headb_b);
    k_head<<<1, 256>>>(head_w, head_b, (float*)d_out);
}